// round 17
// baseline (speedup 1.0000x reference)
#include <cuda_runtime.h>

// Screen geometry (must match reference exactly, as float32)
#define NX 1024
#define NY 1024
__device__ __constant__ float c_LEFT   = -0.00512f;
__device__ __constant__ float c_RIGHT  =  0.00512f;
__device__ __constant__ float c_BOTTOM = -0.00512f;
__device__ __constant__ float c_TOP    =  0.00512f;
__device__ __constant__ float c_HSTEP  =  1e-5f;
__device__ __constant__ float c_VSTEP  =  1e-5f;

#define N_PARTICLES 16777216
#define TPB 256

__global__ void zero_out_kernel(float4* __restrict__ out, int n4) {
    int i = blockIdx.x * blockDim.x + threadIdx.x;
    if (i < n4) out[i] = make_float4(0.f, 0.f, 0.f, 0.f);
}

// Predicated fire-and-forget RED: issues for all lanes, adds only where a!=0.
// Inline PTX forces @q RED (no BSSY/BSYNC branch overhead).
__device__ __forceinline__ void red_if(int a, float* p) {
    asm volatile(
        "{\n\t"
        ".reg .pred q;\n\t"
        "setp.ne.s32 q, %0, 0;\n\t"
        "@q red.global.add.f32 [%1], %2;\n\t"
        "}"
        :: "r"(a), "l"(p), "f"(1.0f) : "memory");
}

__global__ void __launch_bounds__(TPB)
hist_kernel(const float4* __restrict__ xs4, const float4* __restrict__ ys4,
            const float* __restrict__ mis, float* __restrict__ out) {
    int i = blockIdx.x * blockDim.x + threadIdx.x;  // one float4 per thread
    unsigned lane = threadIdx.x & 31u;
    float mx = mis[0];
    float my = mis[1];
    float4 x4 = xs4[i];
    float4 y4 = ys4[i];

    float px[4] = {x4.x - mx, x4.y - mx, x4.z - mx, x4.w - mx};
    float py[4] = {y4.x - my, y4.y - my, y4.z - my, y4.w - my};
    float* addr[4];
    int    act[4];
#pragma unroll
    for (int j = 0; j < 4; j++) {
        float x = px[j], y = py[j];
        // Match jnp.floor((x - LEFT)/HSTEP) in fp32, IEEE round-to-nearest division.
        act[j] = (x >= c_LEFT) & (x <= c_RIGHT) & (y >= c_BOTTOM) & (y <= c_TOP);
        int ix = (int)floorf(__fdiv_rn(x - c_LEFT,   c_HSTEP));
        int iy = (int)floorf(__fdiv_rn(y - c_BOTTOM, c_VSTEP));
        if (x == c_RIGHT) ix = NX - 1;
        if (y == c_TOP)   iy = NY - 1;
        ix = min(max(ix, 0), NX - 1);
        iy = min(max(iy, 0), NY - 1);
        addr[j] = out + ((NY - 1 - iy) * NX + ix);
    }

    // Single-active-lane REDs: 32 rounds, lane k deposits its 4 particles in
    // round k. Each RED instruction carries exactly one wavefront -> rides the
    // ~1.0 cyc/wf cross-instruction L1tex path instead of 2.07 cyc/wf replays.
#pragma unroll
    for (int k = 0; k < 32; k++) {
        int lk = (lane == (unsigned)k);
        red_if(act[0] & lk, addr[0]);
        red_if(act[1] & lk, addr[1]);
        red_if(act[2] & lk, addr[2]);
        red_if(act[3] & lk, addr[3]);
    }
}

extern "C" void kernel_launch(void* const* d_in, const int* in_sizes, int n_in,
                              void* d_out, int out_size) {
    const float* xs  = (const float*)d_in[0];
    const float* ys  = (const float*)d_in[1];
    const float* mis = (const float*)d_in[2];
    float* out = (float*)d_out;

    // 1) zero the image (out_size = NX*NY floats, divisible by 4)
    int n4 = out_size / 4;
    zero_out_kernel<<<(n4 + 255) / 256, 256>>>((float4*)out, n4);

    // 2) histogram: 16,777,216 particles, 4 per thread
    int work = N_PARTICLES / 4;          // 4,194,304 threads
    hist_kernel<<<work / TPB, TPB>>>((const float4*)xs, (const float4*)ys, mis, out);
}